// round 15
// baseline (speedup 1.0000x reference)
#include <cuda_runtime.h>
#include <cuda_fp16.h>

// VIN fully fused — HFMA2, 384 threads (3 warps/SMSP) WITH register
// headroom (~130 live < 170 cap): the combination never yet tested.
//  r   = conv3x3(X, W_eff) + b_eff      (fp32, 150-ch hidden collapsed)
//  qr  = conv3x3(r, q_w)  fp32, quantized once to half2 ch-pairs (2j,2j+1)
//  v0  = max_l qr[l]
//  39x: v = max_l ( qr[l] + conv3x3(v, w[l]) )   [fp16x2]
// Thread = column x, 11-row band (6 bands, writes predicated y<64).
// v duplicated (v,v) half2 col-major stride 67 (odd, conflict-free);
// qr col-major stride 68 half2, scalar reads. Double-buffer, 1 barrier/iter.

#define THREADS 384
#define NPX     4096
#define LQ      10
#define LH      150
#define QSH     68                    // qr col stride (half2); odd
#define PPLH    (64 * QSH)            // qr plane stride = 4352 half2
#define SVH     67                    // v col stride (half2), odd
#define V_FH    (66 * SVH + 2)        // 4424 half2 per buffer
#define RW      72                    // rbuf row stride (fp32, prologue)
#define RB_F    (66 * RW)             // 4752 fp32; vB aliases rbuf region
#define SMEM_BYTES ((5 * PPLH + V_FH) * 4 + RB_F * 4)   // ~120.8 KB

__global__ void __launch_bounds__(THREADS, 1)
vin_h384_kernel(const float* __restrict__ X, const float* __restrict__ h_w,
                const float* __restrict__ h_b, const float* __restrict__ r_w,
                const float* __restrict__ q_w, const float* __restrict__ ww,
                const int* __restrict__ kptr, float* __restrict__ out)
{
    extern __shared__ float smem[];
    __half2* qrh = (__half2*)smem;               // [5][PPLH] ch-pair planes
    __half2* vA  = qrh + 5 * PPLH;               // [V_FH] (v,v) pairs
    float*   rbuf = (float*)(vA + V_FH);         // [RB_F] fp32, prologue only
    __half2* vB  = (__half2*)rbuf;               // aliases rbuf
    __shared__ float   s_weff[19];
    __shared__ float   s_qw[LQ * 9];
    __shared__ __half2 s_wph[45];                // packed loop weights

    const int tid = threadIdx.x;
    const int b   = blockIdx.x;
    const float* Xb = X + (size_t)b * 2 * NPX;

    // ---- stage weights; collapse hidden layer ----
    if (tid < LQ * 9) s_qw[tid] = q_w[tid];
    if (tid < 45) {
        int j = tid / 9, t = tid % 9;
        s_wph[tid] = __floats2half2_rn(ww[(2 * j) * 9 + t], ww[(2 * j + 1) * 9 + t]);
    }
    if (tid < 19) {
        float acc = 0.f;
        if (tid < 18) { for (int l = 0; l < LH; ++l) acc += r_w[l] * h_w[l * 18 + tid]; }
        else          { for (int l = 0; l < LH; ++l) acc += r_w[l] * h_b[l]; }
        s_weff[tid] = acc;
    }
    {
        const __half2 z = __float2half2_rn(0.f);
        for (int i = tid; i < V_FH; i += THREADS) vA[i] = z;
    }
    for (int i = tid; i < RB_F; i += THREADS) rbuf[i] = 0.f;
    __syncthreads();

    // ---- r = conv3x3(X, W_eff) + b_eff (fp32, rbuf row-major) ----
    for (int px = tid; px < NPX; px += THREADS) {
        int y = px >> 6, x = px & 63;
        float acc = s_weff[18];
        #pragma unroll
        for (int c = 0; c < 2; ++c)
            #pragma unroll
            for (int ky = 0; ky < 3; ++ky) {
                int iy = y - 1 + ky;
                if (iy < 0 || iy >= 64) continue;
                #pragma unroll
                for (int kx = 0; kx < 3; ++kx) {
                    int ix = x - 1 + kx;
                    if (ix < 0 || ix >= 64) continue;
                    acc += s_weff[c * 9 + ky * 3 + kx] * Xb[c * NPX + iy * 64 + ix];
                }
            }
        rbuf[(y + 1) * RW + x + 1] = acc;
    }
    __syncthreads();

    // ---- qr (fp32 -> half2 pairs, col-major) + v0 into vA ----
    for (int idx = tid; idx < NPX; idx += THREADS) {
        int x = idx >> 6, y = idx & 63;      // y-major: contiguous col stores
        float n[9];
        #pragma unroll
        for (int ky = 0; ky < 3; ++ky)
            #pragma unroll
            for (int kx = 0; kx < 3; ++kx)
                n[ky * 3 + kx] = rbuf[(y + ky) * RW + x + kx];
        float s[LQ];
        float vmax = -1e30f;
        #pragma unroll
        for (int l = 0; l < LQ; ++l) {
            float a = 0.f;
            #pragma unroll
            for (int t = 0; t < 9; ++t) a += s_qw[l * 9 + t] * n[t];
            s[l] = a;
            vmax = fmaxf(vmax, a);
        }
        #pragma unroll
        for (int j = 0; j < 5; ++j)
            qrh[j * PPLH + x * QSH + y] = __floats2half2_rn(s[2 * j], s[2 * j + 1]);
        vA[(x + 1) * SVH + (y + 1)] = __float2half2_rn(vmax);
    }
    __syncthreads();

    // ---- zero vB (aliased rbuf; ghosts must be 0) ----
    {
        const __half2 z = __float2half2_rn(0.f);
        for (int i = tid; i < V_FH; i += THREADS) vB[i] = z;
    }

    // ---- hoist all 45 packed weights into registers ----
    __half2 wp[45];
    #pragma unroll
    for (int i = 0; i < 45; ++i) wp[i] = s_wph[i];

    const int k  = kptr[0];
    const int x  = tid % 64;              // column
    const int y0 = (tid / 64) * 11;       // band: 6 bands x 11 rows (66>=64)
    const int nvalid = (y0 + 11 <= 64) ? 11 : (64 - y0);   // 11 or 9
    const __half2* qc = qrh + x * QSH + y0;
    __half2* cur = vA;
    __half2* alt = vB;
    const __half2 NEG = __float2half2_rn(-60000.f);
    __syncthreads();                      // vB zeroed

    // ---- value iteration ----
    for (int it = 0; it < k - 1; ++it) {
        // window: 3 cols (x-1,x,x+1 -> idx x..x+2), 13 rows (v rows
        // y0-1..y0+11 -> v idx y0..y0+12); scalar LDS, conflict-free.
        __half2 wn[3][13];
        #pragma unroll
        for (int c = 0; c < 3; ++c) {
            const __half2* colp = cur + (x + c) * SVH + y0;
            #pragma unroll
            for (int j = 0; j < 13; ++j) wn[c][j] = colp[j];
        }
        __half2 m[11];
        #pragma unroll
        for (int y = 0; y < 11; ++y) m[y] = NEG;

        #pragma unroll
        for (int j = 0; j < 5; ++j) {
            __half2 qf[11];
            #pragma unroll
            for (int y = 0; y < 11; ++y) qf[y] = qc[j * PPLH + y];
            #pragma unroll
            for (int y = 0; y < 11; ++y) {
                __half2 a = qf[y];
                a = __hfma2(wn[0][y],     wp[j * 9 + 0], a);
                a = __hfma2(wn[1][y],     wp[j * 9 + 1], a);
                a = __hfma2(wn[2][y],     wp[j * 9 + 2], a);
                a = __hfma2(wn[0][y + 1], wp[j * 9 + 3], a);
                a = __hfma2(wn[1][y + 1], wp[j * 9 + 4], a);
                a = __hfma2(wn[2][y + 1], wp[j * 9 + 5], a);
                a = __hfma2(wn[0][y + 2], wp[j * 9 + 6], a);
                a = __hfma2(wn[1][y + 2], wp[j * 9 + 7], a);
                a = __hfma2(wn[2][y + 2], wp[j * 9 + 8], a);
                m[y] = __hmax2(m[y], a);
            }
        }
        // fold lanes -> duplicated (m,m); predicated scalar STS
        {
            __half2* wc = alt + (x + 1) * SVH + y0 + 1;
            #pragma unroll
            for (int y = 0; y < 11; ++y)
                if (y < nvalid)
                    wc[y] = __hmax2(m[y], __lowhigh2highlow(m[y]));
        }
        __syncthreads();                  // alt complete; cur reads done
        __half2* t = cur; cur = alt; alt = t;
    }

    // ---- output [B,1,64,64] fp32 from cur ----
    for (int px = tid; px < NPX; px += THREADS) {
        int y = px >> 6, xx = px & 63;
        out[(size_t)b * NPX + px] = __low2float(cur[(xx + 1) * SVH + (y + 1)]);
    }
}

extern "C" void kernel_launch(void* const* d_in, const int* in_sizes, int n_in,
                              void* d_out, int out_size) {
    const float* X   = (const float*)d_in[0];
    const float* h_w = (const float*)d_in[1];
    const float* h_b = (const float*)d_in[2];
    const float* r_w = (const float*)d_in[3];
    const float* q_w = (const float*)d_in[4];
    const float* w_  = (const float*)d_in[5];
    const int*   k   = (const int*)d_in[6];

    int B = in_sizes[0] / (2 * NPX);   // 128

    cudaFuncSetAttribute(vin_h384_kernel,
                         cudaFuncAttributeMaxDynamicSharedMemorySize, SMEM_BYTES);
    vin_h384_kernel<<<B, THREADS, SMEM_BYTES>>>(X, h_w, h_b, r_w, q_w, w_, k,
                                                (float*)d_out);
}

// round 16
// speedup vs baseline: 1.6995x; 1.6995x over previous
#include <cuda_runtime.h>
#include <cuda_fp16.h>

// VIN fully fused — HFMA2, 256 threads, qr RESIDENT in registers and own
// output column carried across iterations (res[] regs), minimizing per-iter
// SMEM traffic to 38 LDS + 16 STS.
//  r   = conv3x3(X, W_eff) + b_eff      (fp32, 150-ch hidden collapsed)
//  qr  = conv3x3(r, q_w)  fp32, quantized once to half2 ch-pairs (2j,2j+1)
//  v0  = max_l qr[l]
//  39x: v = max_l ( qr[l] + conv3x3(v, w[l]) )   [fp16x2]
// Thread = column x, 16-row band (4 bands, exact). v duplicated (v,v) half2
// col-major stride 67 (odd, conflict-free); qr col-major stride 68 half2
// (16B-aligned LDS.128, loaded ONCE). Double-buffered v, 1 barrier/iter.

#define THREADS 256
#define NPX     4096
#define LQ      10
#define LH      150
#define QSH     68                    // qr col stride (half2); 17x16B odd
#define PPLH    (64 * QSH)            // qr plane stride = 4352 half2
#define SVH     67                    // v col stride (half2), odd
#define V_FH    (66 * SVH + 2)        // 4424 half2 per buffer
#define RW      72                    // rbuf row stride (fp32, prologue)
#define RB_F    (66 * RW)             // 4752 fp32; vB aliases rbuf region
#define SMEM_BYTES ((5 * PPLH + V_FH) * 4 + RB_F * 4)   // ~120.8 KB

__global__ void __launch_bounds__(THREADS, 1)
vin_hres_kernel(const float* __restrict__ X, const float* __restrict__ h_w,
                const float* __restrict__ h_b, const float* __restrict__ r_w,
                const float* __restrict__ q_w, const float* __restrict__ ww,
                const int* __restrict__ kptr, float* __restrict__ out)
{
    extern __shared__ float smem[];
    __half2* qrh = (__half2*)smem;               // [5][PPLH] ch-pair planes
    __half2* vA  = qrh + 5 * PPLH;               // [V_FH] (v,v) pairs
    float*   rbuf = (float*)(vA + V_FH);         // [RB_F] fp32, prologue only
    __half2* vB  = (__half2*)rbuf;               // aliases rbuf
    __shared__ float   s_weff[19];
    __shared__ float   s_qw[LQ * 9];
    __shared__ __half2 s_wph[45];                // packed loop weights

    const int tid = threadIdx.x;
    const int b   = blockIdx.x;
    const float* Xb = X + (size_t)b * 2 * NPX;

    // ---- stage weights; collapse hidden layer ----
    if (tid < LQ * 9) s_qw[tid] = q_w[tid];
    if (tid < 45) {
        int j = tid / 9, t = tid % 9;
        s_wph[tid] = __floats2half2_rn(ww[(2 * j) * 9 + t], ww[(2 * j + 1) * 9 + t]);
    }
    if (tid < 19) {
        float acc = 0.f;
        if (tid < 18) { for (int l = 0; l < LH; ++l) acc += r_w[l] * h_w[l * 18 + tid]; }
        else          { for (int l = 0; l < LH; ++l) acc += r_w[l] * h_b[l]; }
        s_weff[tid] = acc;
    }
    {
        const __half2 z = __float2half2_rn(0.f);
        for (int i = tid; i < V_FH; i += THREADS) vA[i] = z;
    }
    for (int i = tid; i < RB_F; i += THREADS) rbuf[i] = 0.f;
    __syncthreads();

    // ---- r = conv3x3(X, W_eff) + b_eff (fp32, rbuf row-major) ----
    for (int px = tid; px < NPX; px += THREADS) {
        int y = px >> 6, x = px & 63;
        float acc = s_weff[18];
        #pragma unroll
        for (int c = 0; c < 2; ++c)
            #pragma unroll
            for (int ky = 0; ky < 3; ++ky) {
                int iy = y - 1 + ky;
                if (iy < 0 || iy >= 64) continue;
                #pragma unroll
                for (int kx = 0; kx < 3; ++kx) {
                    int ix = x - 1 + kx;
                    if (ix < 0 || ix >= 64) continue;
                    acc += s_weff[c * 9 + ky * 3 + kx] * Xb[c * NPX + iy * 64 + ix];
                }
            }
        rbuf[(y + 1) * RW + x + 1] = acc;
    }
    __syncthreads();

    // ---- qr (fp32 -> half2 pairs, col-major) + v0 into vA ----
    for (int idx = tid; idx < NPX; idx += THREADS) {
        int x = idx >> 6, y = idx & 63;      // y-major: contiguous col stores
        float n[9];
        #pragma unroll
        for (int ky = 0; ky < 3; ++ky)
            #pragma unroll
            for (int kx = 0; kx < 3; ++kx)
                n[ky * 3 + kx] = rbuf[(y + ky) * RW + x + kx];
        float s[LQ];
        float vmax = -1e30f;
        #pragma unroll
        for (int l = 0; l < LQ; ++l) {
            float a = 0.f;
            #pragma unroll
            for (int t = 0; t < 9; ++t) a += s_qw[l * 9 + t] * n[t];
            s[l] = a;
            vmax = fmaxf(vmax, a);
        }
        #pragma unroll
        for (int j = 0; j < 5; ++j)
            qrh[j * PPLH + x * QSH + y] = __floats2half2_rn(s[2 * j], s[2 * j + 1]);
        vA[(x + 1) * SVH + (y + 1)] = __float2half2_rn(vmax);
    }
    __syncthreads();

    // ---- zero vB (aliased rbuf; ghosts must be 0) ----
    {
        const __half2 z = __float2half2_rn(0.f);
        for (int i = tid; i < V_FH; i += THREADS) vB[i] = z;
    }

    // ---- hoist 45 packed weights ----
    __half2 wp[45];
    #pragma unroll
    for (int i = 0; i < 45; ++i) wp[i] = s_wph[i];

    const int k  = kptr[0];
    const int x  = tid & 63;              // column
    const int y0 = (tid >> 6) << 4;       // band: 4 bands x 16 rows, exact
    __half2* cur = vA;
    __half2* alt = vB;

    // ---- qr RESIDENT: 5 pairs x 16 rows, loaded once (aligned LDS.128) ----
    __half2 qf[5][16];
    {
        const __half2* qc = qrh + x * QSH + y0;
        #pragma unroll
        for (int j = 0; j < 5; ++j)
            #pragma unroll
            for (int q4 = 0; q4 < 4; ++q4) {
                uint4 qa = *(const uint4*)(qc + j * PPLH + 4 * q4);
                qf[j][4 * q4 + 0] = *(__half2*)&qa.x;
                qf[j][4 * q4 + 1] = *(__half2*)&qa.y;
                qf[j][4 * q4 + 2] = *(__half2*)&qa.z;
                qf[j][4 * q4 + 3] = *(__half2*)&qa.w;
            }
    }
    // ---- own output column resident across iterations ----
    __half2 res[16];
    #pragma unroll
    for (int y = 0; y < 16; ++y) res[y] = cur[(x + 1) * SVH + y0 + 1 + y];

    __syncthreads();                      // vB zeroed

    // ---- value iteration ----
    for (int it = 0; it < k - 1; ++it) {
        // side columns: 18 rows each (v idx y0..y0+17); middle column =
        // res[] + 2 boundary rows. All scalar LDS, odd stride, conflict-free.
        __half2 wn0[18], wn2[18];
        {
            const __half2* c0 = cur + x * SVH + y0;
            const __half2* c2 = cur + (x + 2) * SVH + y0;
            #pragma unroll
            for (int j = 0; j < 18; ++j) { wn0[j] = c0[j]; wn2[j] = c2[j]; }
        }
        __half2 wn1[18];
        wn1[0]  = cur[(x + 1) * SVH + y0];         // row y0-1
        wn1[17] = cur[(x + 1) * SVH + y0 + 17];    // row y0+16
        #pragma unroll
        for (int y = 0; y < 16; ++y) wn1[y + 1] = res[y];

        __half2 m[16];
        #pragma unroll
        for (int j = 0; j < 5; ++j) {
            #pragma unroll
            for (int y = 0; y < 16; ++y) {
                __half2 a = qf[j][y];
                a = __hfma2(wn0[y],     wp[j * 9 + 0], a);
                a = __hfma2(wn1[y],     wp[j * 9 + 1], a);
                a = __hfma2(wn2[y],     wp[j * 9 + 2], a);
                a = __hfma2(wn0[y + 1], wp[j * 9 + 3], a);
                a = __hfma2(wn1[y + 1], wp[j * 9 + 4], a);
                a = __hfma2(wn2[y + 1], wp[j * 9 + 5], a);
                a = __hfma2(wn0[y + 2], wp[j * 9 + 6], a);
                a = __hfma2(wn1[y + 2], wp[j * 9 + 7], a);
                a = __hfma2(wn2[y + 2], wp[j * 9 + 8], a);
                m[y] = (j == 0) ? a : __hmax2(m[y], a);
            }
        }
        // fold lanes -> duplicated (m,m); keep in res, store to alt
        {
            __half2* wc = alt + (x + 1) * SVH + y0 + 1;
            #pragma unroll
            for (int y = 0; y < 16; ++y) {
                res[y] = __hmax2(m[y], __lowhigh2highlow(m[y]));
                wc[y] = res[y];
            }
        }
        __syncthreads();                  // alt complete; cur reads done
        __half2* t = cur; cur = alt; alt = t;
    }

    // ---- output [B,1,64,64] fp32 from cur ----
    for (int px = tid; px < NPX; px += THREADS) {
        int y = px >> 6, xx = px & 63;
        out[(size_t)b * NPX + px] = __low2float(cur[(xx + 1) * SVH + (y + 1)]);
    }
}

extern "C" void kernel_launch(void* const* d_in, const int* in_sizes, int n_in,
                              void* d_out, int out_size) {
    const float* X   = (const float*)d_in[0];
    const float* h_w = (const float*)d_in[1];
    const float* h_b = (const float*)d_in[2];
    const float* r_w = (const float*)d_in[3];
    const float* q_w = (const float*)d_in[4];
    const float* w_  = (const float*)d_in[5];
    const int*   k   = (const int*)d_in[6];

    int B = in_sizes[0] / (2 * NPX);   // 128

    cudaFuncSetAttribute(vin_hres_kernel,
                         cudaFuncAttributeMaxDynamicSharedMemorySize, SMEM_BYTES);
    vin_hres_kernel<<<B, THREADS, SMEM_BYTES>>>(X, h_w, h_b, r_w, q_w, w_, k,
                                                (float*)d_out);
}